// round 16
// baseline (speedup 1.0000x reference)
#include <cuda_runtime.h>
#include <cuda_bf16.h>
#include <math.h>
#include <stdint.h>

#define NE 4
#define NB 8192
#define NF 2048
#define NL 100
#define NEB (NE*NB)
#define LAM 1.0f
#define NPAD 112           // CE N padding (14 n8-tiles)
#define NBZ 4              // batch splits (partial-sum copies)
#define NTILES 512

// ---------------- device scratch (no allocations allowed) ----------------
__device__ float  g_sums_part[NBZ*NE*NL*NF];   // written fully each launch
__device__ float  g_counts[NE*NL];
__device__ float  g_var[NE*NL];
__device__ float  g_visit[NE*NL];
__device__ double g_ce;
__device__ unsigned g_done;
__device__ unsigned g_ticket;
__device__ __align__(16) __nv_bfloat16 g_Wb[NPAD*NF];  // W^T bf16 [n][k], n>=100 zero

// ======================= PTX helpers (sm_80-compatible) ==================
__device__ __forceinline__ uint32_t smem_u32(const void* p) {
    return (uint32_t)__cvta_generic_to_shared(p);
}
__device__ __forceinline__ uint32_t swz128(uint32_t off) {   // 128B-row swizzle
    return off ^ ((off >> 3) & 0x70u);
}
__device__ __forceinline__ uint32_t swz256(uint32_t off) {   // 256B-row swizzle
    return off ^ ((off >> 4) & 0xF0u);
}
__device__ __forceinline__ void cp16(uint32_t dst, const void* src) {
    asm volatile("cp.async.cg.shared.global [%0], [%1], 16;" :: "r"(dst), "l"(src));
}
__device__ __forceinline__ void cp_commit() {
    asm volatile("cp.async.commit_group;" ::: "memory");
}
__device__ __forceinline__ void cp_wait1() {
    asm volatile("cp.async.wait_group 1;" ::: "memory");
}
__device__ __forceinline__ void cp_wait0() {
    asm volatile("cp.async.wait_group 0;" ::: "memory");
}
__device__ __forceinline__ void ldm_x4(uint32_t* r, uint32_t a) {
    asm volatile("ldmatrix.sync.aligned.m8n8.x4.shared.b16 {%0,%1,%2,%3}, [%4];"
                 : "=r"(r[0]), "=r"(r[1]), "=r"(r[2]), "=r"(r[3]) : "r"(a));
}
__device__ __forceinline__ void ldm_x2t(uint32_t* r, uint32_t a) {
    asm volatile("ldmatrix.sync.aligned.m8n8.x2.trans.shared.b16 {%0,%1}, [%2];"
                 : "=r"(r[0]), "=r"(r[1]) : "r"(a));
}
__device__ __forceinline__ void mma16816(float* c, const uint32_t* a, const uint32_t* b) {
    asm volatile(
        "mma.sync.aligned.m16n8k16.row.col.f32.bf16.bf16.f32 "
        "{%0,%1,%2,%3}, {%4,%5,%6,%7}, {%8,%9}, {%0,%1,%2,%3};"
        : "+f"(c[0]), "+f"(c[1]), "+f"(c[2]), "+f"(c[3])
        : "r"(a[0]), "r"(a[1]), "r"(a[2]), "r"(a[3]), "r"(b[0]), "r"(b[1]));
}
__device__ __forceinline__ uint2 cvt_f4_bf16x4(float4 v) {
    __nv_bfloat162 lo = __float22bfloat162_rn(make_float2(v.x, v.y));
    __nv_bfloat162 hi = __float22bfloat162_rn(make_float2(v.z, v.w));
    return make_uint2(*(uint32_t*)&lo, *(uint32_t*)&hi);
}
__device__ __forceinline__ uint32_t cvt2(float2 v) {
    __nv_bfloat162 t = __float22bfloat162_rn(v);
    return *(uint32_t*)&t;
}

#define NCHUNK (NF/64)   // 32
#define SCHUNK 32
#define ONE2 0x3F803F80u
#define BSTAGE 14336                      // 112 rows x 128 B
#define FAT_SMEM (1024 + 3*BSTAGE)        // 44032; sums side uses 37888

// ===== setup: prep W^T bf16 + zero misc (one launch) =====================
__global__ void setup_kernel(const float* __restrict__ W) {
    const int bx = blockIdx.x, tid = threadIdx.x;
    if (bx < 896) {
        int i = bx*256 + tid;              // 0..229375
        int n = i >> 11;
        int k = i & (NF-1);
        float v = (n < NL) ? W[(size_t)k*NL + n] : 0.f;
        g_Wb[i] = __float2bfloat16(v);
    } else {
        if (tid < NE*NL) g_counts[tid] = 0.f;
        if (tid == 0) { g_ce = 0.0; g_done = 0u; g_ticket = 0u; }
    }
}

// ==== persistent fat kernel: CE GEMM + sums GEMM via dynamic scheduler ===
// grid = 296 (148 SMs x 2 CTAs); tickets 0..511: even -> CE, odd -> sums
__global__ void __launch_bounds__(256, 2)
fat_kernel(const float* __restrict__ feats,
           const int*   __restrict__ y,
           const float* __restrict__ b) {
    const int tid = threadIdx.x;

    extern __shared__ char smx[];
    const uint32_t tile0 = (smem_u32(smx) + 1023u) & ~1023u;
    const int wid  = tid >> 5;
    const int lane = tid & 31;
    const int lq   = lane & 3;
    const int lr4  = lane >> 2;
    const float4* fv = (const float4*)feats;

    __shared__ int s_bx;

    for (;;) {
        if (tid == 0) s_bx = (int)atomicAdd(&g_ticket, 1u);
        __syncthreads();
        const int bx = s_bx;
        if (bx >= NTILES) return;
        __syncthreads();   // all threads past the read before smem reuse

        if ((bx & 1) == 0) {
            // ====== CE GEMM: warp = 16-row band x 112 cols (14 tiles) =====
            const uint32_t tB[3] = { tile0, tile0 + BSTAGE, tile0 + 2*BSTAGE };
            __shared__ float bias_s[NPAD];
            __shared__ float redw[8];

            const int m0 = (bx >> 1) * 128;
            if (tid < NPAD) bias_s[tid] = (tid < NL) ? b[tid] : 0.f;

            float acc[14][4];
            #pragma unroll
            for (int nt = 0; nt < 14; nt++)
                #pragma unroll
                for (int j = 0; j < 4; j++) acc[nt][j] = 0.f;

            const float* aptr0 = feats + (size_t)(m0 + wid*16 + lr4) * NF + 2*lq;
            const float* aptr1 = aptr0 + 8*(size_t)NF;
            float2 sa[16];

            auto loadA = [&](int kt, int jlo, int jhi) {
                #pragma unroll
                for (int j = jlo; j < jhi; j++) {
                    sa[2*j]   = *(const float2*)(aptr0 + kt*64 + 8*j);
                    sa[2*j+1] = *(const float2*)(aptr1 + kt*64 + 8*j);
                }
            };
            auto issueB = [&](int kt, int stg) {   // 112 n x 64 k = 896 cp16
                #pragma unroll
                for (int i = 0; i < 4; i++) {
                    int idx = i*256 + tid;
                    if (idx < 896) {
                        int n = idx >> 3, q = idx & 7;
                        cp16(tB[stg] + swz128((uint32_t)(n*128 + q*16)),
                             g_Wb + (size_t)n*NF + kt*64 + q*8);
                    }
                }
                cp_commit();
            };

            const int l7    = lane & 7;
            const int khalf = (lane >> 3) & 1;
            const int npair = (lane >> 4) & 1;

            issueB(0, 0);
            issueB(1, 1);
            loadA(0, 0, 8);

            for (int kt = 0; kt < NCHUNK; kt++) {
                const int sb = kt % 3;
                if (kt + 1 < NCHUNK) cp_wait1(); else cp_wait0();
                __syncthreads();
                if (kt + 2 < NCHUNK) issueB(kt + 2, (kt + 2) % 3);
                const bool more = (kt + 1 < NCHUNK);

                #pragma unroll
                for (int s = 0; s < 4; s++) {
                    uint32_t af[4];
                    af[0] = cvt2(sa[4*s + 0]);
                    af[1] = cvt2(sa[4*s + 1]);
                    af[2] = cvt2(sa[4*s + 2]);
                    af[3] = cvt2(sa[4*s + 3]);
                    uint32_t bf[14][2];
                    #pragma unroll
                    for (int nt = 0; nt < 14; nt += 2) {
                        uint32_t row = (uint32_t)(nt*8 + npair*8 + l7);
                        uint32_t boff = (uint32_t)(s*32 + khalf*16);
                        uint32_t r4[4];
                        ldm_x4(r4, tB[sb] + swz128(row*128 + boff));
                        bf[nt][0] = r4[0];   bf[nt][1] = r4[1];
                        bf[nt+1][0] = r4[2]; bf[nt+1][1] = r4[3];
                    }
                    if (s == 1 && more) loadA(kt + 1, 0, 4);
                    #pragma unroll
                    for (int nt = 0; nt < 14; nt++)
                        mma16816(acc[nt], af, bf[nt]);
                    if (s == 3 && more) loadA(kt + 1, 4, 8);
                }
            }

            // -------- warp-local CE epilogue --------
            float ce = 0.f;
            #pragma unroll
            for (int h = 0; h < 2; h++) {
                int row = m0 + wid*16 + h*8 + lr4;
                int yv = y[row];
                float mx = -1e30f, own = 0.f;
                #pragma unroll
                for (int nt = 0; nt < 14; nt++) {
                    #pragma unroll
                    for (int j = 0; j < 2; j++) {
                        int gc = nt*8 + 2*lq + j;
                        float v = acc[nt][h*2 + j] + bias_s[gc];
                        if (gc >= NL) v = -1e30f;
                        mx = fmaxf(mx, v);
                        if (gc == yv) own = v;
                    }
                }
                mx = fmaxf(mx, __shfl_xor_sync(0xffffffffu, mx, 1));
                mx = fmaxf(mx, __shfl_xor_sync(0xffffffffu, mx, 2));
                own += __shfl_xor_sync(0xffffffffu, own, 1);
                own += __shfl_xor_sync(0xffffffffu, own, 2);
                float se = 0.f;
                #pragma unroll
                for (int nt = 0; nt < 14; nt++) {
                    #pragma unroll
                    for (int j = 0; j < 2; j++) {
                        int gc = nt*8 + 2*lq + j;
                        float v = acc[nt][h*2 + j] + bias_s[gc];
                        if (gc < NL) se += __expf(v - mx);
                    }
                }
                se += __shfl_xor_sync(0xffffffffu, se, 1);
                se += __shfl_xor_sync(0xffffffffu, se, 2);
                if (lq == 0) ce += mx + __logf(se) - own;
            }
            #pragma unroll
            for (int o = 16; o > 0; o >>= 1)
                ce += __shfl_xor_sync(0xffffffffu, ce, o);
            if (lane == 0) redw[wid] = ce;
            __syncthreads();
            if (tid == 0) {
                float t = 0.f;
                #pragma unroll
                for (int w = 0; w < 8; w++) t += redw[w];
                atomicAdd(&g_ce, (double)t);
            }
            __syncthreads();
        } else {
            // ====== sums GEMM: partial[bz][e] = onehot^T @ feats slice ====
            const uint32_t tF[2] = { tile0, tile0 + 16384 };
            uint32_t* sy16 = (uint32_t*)(smx + (tile0 - smem_u32(smx)) + 32768);

            const int blk = bx >> 1;
            const int n0  = (blk & 15) * 128;
            const int e   = (blk >> 4) & 3;
            const int bzi = (blk >> 6);
            const int bz  = bzi * 2048;
            const int wm  = wid >> 1;
            const int wn  = wid & 1;

            {
                const int* yp = y + e*NB + bz;
                for (int j = tid; j < 1024; j += 256)
                    sy16[j] = (uint32_t)yp[2*j] | ((uint32_t)yp[2*j + 1] << 16);
            }

            float acc[2][8][4];
            #pragma unroll
            for (int mt = 0; mt < 2; mt++)
                #pragma unroll
                for (int nt = 0; nt < 8; nt++)
                    #pragma unroll
                    for (int j = 0; j < 4; j++) acc[mt][nt][j] = 0.f;

            uint2 st[8];
            auto load_regs = [&](int kt) {
                #pragma unroll
                for (int i = 0; i < 8; i++) {
                    int idx = i*256 + tid;
                    int row = idx >> 5, q = idx & 31;
                    st[i] = cvt_f4_bf16x4(
                        fv[(size_t)(e*NB + bz + kt*64 + row)*(NF/4) + (n0 >> 2) + q]);
                }
            };
            auto sts_regs = [&](int s) {
                #pragma unroll
                for (int i = 0; i < 8; i++) {
                    int idx = i*256 + tid;
                    int row = idx >> 5, q = idx & 31;
                    asm volatile("st.shared.v2.u32 [%0], {%1, %2};"
                                 :: "r"(tF[s] + swz256((uint32_t)(row*256 + q*8))),
                                    "r"(st[i].x), "r"(st[i].y) : "memory");
                }
            };

            load_regs(0);

            for (int kt = 0; kt < SCHUNK; kt++) {
                const int s = kt & 1;
                sts_regs(s);
                if (kt + 1 < SCHUNK) load_regs(kt + 1);
                __syncthreads();

                #pragma unroll
                for (int k16 = 0; k16 < 4; k16++) {
                    uint32_t bfr[8][2];
                    {
                        int rr = k16*16 + (lane & 15);
                        #pragma unroll
                        for (int nt = 0; nt < 8; nt++) {
                            uint32_t cn = (uint32_t)(wn*8 + nt);
                            ldm_x2t(bfr[nt], tF[s] + swz256((uint32_t)(rr*256) + cn*16));
                        }
                    }
                    uint32_t yp0 = sy16[kt*32 + k16*8 + lq];
                    uint32_t yp1 = sy16[kt*32 + k16*8 + 4 + lq];
                    #pragma unroll
                    for (int mt = 0; mt < 2; mt++) {
                        int lm = wm*32 + mt*16 + lr4;
                        uint32_t ll  = (uint32_t)lm | ((uint32_t)lm << 16);
                        uint32_t ll8 = ll + 0x00080008u;
                        uint32_t af[4];
                        af[0] = __vcmpeq2(yp0, ll)  & ONE2;
                        af[1] = __vcmpeq2(yp0, ll8) & ONE2;
                        af[2] = __vcmpeq2(yp1, ll)  & ONE2;
                        af[3] = __vcmpeq2(yp1, ll8) & ONE2;
                        #pragma unroll
                        for (int nt = 0; nt < 8; nt++)
                            mma16816(acc[mt][nt], af, bfr[nt]);
                    }
                }
            }

            // ---- flush: plain stores to this (bzi, e)'s private partial --
            float* part = g_sums_part + ((size_t)(bzi*NE + e))*NL*NF;
            #pragma unroll
            for (int mt = 0; mt < 2; mt++) {
                #pragma unroll
                for (int h = 0; h < 2; h++) {
                    int l = wm*32 + mt*16 + h*8 + lr4;
                    if (l < NL) {
                        #pragma unroll
                        for (int nt = 0; nt < 8; nt++) {
                            int f = n0 + wn*64 + nt*8 + 2*lq;
                            *(float2*)(part + (size_t)l*NF + f) =
                                make_float2(acc[mt][nt][h*2 + 0], acc[mt][nt][h*2 + 1]);
                        }
                    }
                }
            }

            // ---- fused label counts (one F-chunk CTA per (e, bz)) ----
            if ((blk & 15) == 0) {
                for (int j = tid; j < 1024; j += 256) {
                    uint32_t u = sy16[j];
                    atomicAdd(&g_counts[e*NL + (int)(u & 0xFFFFu)], 1.0f);
                    atomicAdd(&g_counts[e*NL + (int)(u >> 16)],     1.0f);
                }
            }
            __syncthreads();
        }
    }
}

// ======== variance per (env,label) from 4 partials + final combine ======
__global__ void var_combine_kernel(float* __restrict__ out) {
    const int el = blockIdx.x;                 // e*NL + l
    const int tid = threadIdx.x;
    float cnt = g_counts[el];
    float inv = 1.0f / fmaxf(cnt, 1.0f);
    const float* p0 = g_sums_part + (size_t)(0*NE*NL + el)*NF;
    const float* p1 = g_sums_part + (size_t)(1*NE*NL + el)*NF;
    const float* p2 = g_sums_part + (size_t)(2*NE*NL + el)*NF;
    const float* p3 = g_sums_part + (size_t)(3*NE*NL + el)*NF;

    float sum = 0.f, sq = 0.f;
    for (int f = tid; f < NF; f += 256) {
        float m = (p0[f] + p1[f] + p2[f] + p3[f]) * inv;
        sum += m;
        sq  = fmaf(m, m, sq);
    }
    __shared__ float s1[256], s2[256];
    s1[tid] = sum; s2[tid] = sq;
    __syncthreads();
    for (int o = 128; o > 0; o >>= 1) {
        if (tid < o) { s1[tid] += s1[tid+o]; s2[tid] += s2[tid+o]; }
        __syncthreads();
    }
    __shared__ bool last;
    if (tid == 0) {
        float S = s1[0], Q = s2[0];
        float mu = S / (float)NF;
        g_var[el]   = (Q - S*mu) / (float)(NF - 1);
        g_visit[el] = (cnt > 0.f) ? 1.f : 0.f;
        __threadfence();
        unsigned v = atomicAdd(&g_done, 1u);
        last = (v == (unsigned)(NE*NL - 1));
    }
    __syncthreads();
    if (!last) return;
    __threadfence();

    float pl_sel = 0.f, sel = 0.f;
    if (tid < NL) {
        float nvis = 0.f, vv = 0.f;
        #pragma unroll
        for (int e = 0; e < NE; e++) {
            float vis = g_visit[e*NL + tid];
            nvis += vis;
            vv   += g_var[e*NL + tid] * vis;
        }
        float per = vv / fmaxf(nvis, 1.0f);
        sel    = (nvis > 1.5f) ? 1.f : 0.f;
        pl_sel = per * sel;
    }
    __syncthreads();
    s1[tid] = pl_sel; s2[tid] = sel;
    __syncthreads();
    for (int o = 128; o > 0; o >>= 1) {
        if (tid < o) { s1[tid] += s1[tid+o]; s2[tid] += s2[tid+o]; }
        __syncthreads();
    }
    if (tid == 0) {
        float mean_loss = LAM * s1[0] / fmaxf(s2[0], 1.0f);
        out[0] = mean_loss + (float)(g_ce / (double)NEB);
    }
}

// ---------------- launch ----------------
extern "C" void kernel_launch(void* const* d_in, const int* in_sizes, int n_in,
                              void* d_out, int out_size) {
    const float* feats = (const float*)d_in[0];
    const int*   y     = (const int*)  d_in[1];
    const float* W     = (const float*)d_in[2];
    const float* b     = (const float*)d_in[3];
    float* out = (float*)d_out;

    cudaFuncSetAttribute(fat_kernel, cudaFuncAttributeMaxDynamicSharedMemorySize, FAT_SMEM);

    setup_kernel      <<<897, 256>>>(W);
    fat_kernel        <<<296, 256, FAT_SMEM>>>(feats, y, b);
    var_combine_kernel<<<NE*NL, 256>>>(out);
}

// round 17
// speedup vs baseline: 1.0877x; 1.0877x over previous
#include <cuda_runtime.h>
#include <cuda_bf16.h>
#include <math.h>
#include <stdint.h>

#define NE 4
#define NB 8192
#define NF 2048
#define NL 100
#define NEB (NE*NB)
#define LAM 1.0f
#define NPAD 104           // CE N padding (13 n8-tiles)

// ---------------- device scratch (no allocations allowed) ----------------
__device__ float  g_sums[NE*NL*NF];
__device__ float  g_counts[NE*NL];
__device__ float  g_var[NE*NL];
__device__ float  g_visit[NE*NL];
__device__ double g_ce;
__device__ unsigned g_done;
__device__ __align__(16) __nv_bfloat16 g_Wb[NPAD*NF];  // W^T bf16 [n][k], n>=100 zero

// ======================= PTX helpers (sm_80-compatible) ==================
__device__ __forceinline__ uint32_t smem_u32(const void* p) {
    return (uint32_t)__cvta_generic_to_shared(p);
}
__device__ __forceinline__ uint32_t swz128(uint32_t off) {   // 128B-row swizzle
    return off ^ ((off >> 3) & 0x70u);
}
__device__ __forceinline__ uint32_t swz256(uint32_t off) {   // 256B-row swizzle
    return off ^ ((off >> 4) & 0xF0u);
}
__device__ __forceinline__ void cp16(uint32_t dst, const void* src) {
    asm volatile("cp.async.cg.shared.global [%0], [%1], 16;" :: "r"(dst), "l"(src));
}
__device__ __forceinline__ void cp_commit() {
    asm volatile("cp.async.commit_group;" ::: "memory");
}
__device__ __forceinline__ void cp_wait1() {
    asm volatile("cp.async.wait_group 1;" ::: "memory");
}
__device__ __forceinline__ void cp_wait0() {
    asm volatile("cp.async.wait_group 0;" ::: "memory");
}
__device__ __forceinline__ void ldm_x4(uint32_t* r, uint32_t a) {
    asm volatile("ldmatrix.sync.aligned.m8n8.x4.shared.b16 {%0,%1,%2,%3}, [%4];"
                 : "=r"(r[0]), "=r"(r[1]), "=r"(r[2]), "=r"(r[3]) : "r"(a));
}
__device__ __forceinline__ void ldm_x2(uint32_t* r, uint32_t a) {
    asm volatile("ldmatrix.sync.aligned.m8n8.x2.shared.b16 {%0,%1}, [%2];"
                 : "=r"(r[0]), "=r"(r[1]) : "r"(a));
}
__device__ __forceinline__ void ldm_x2t(uint32_t* r, uint32_t a) {
    asm volatile("ldmatrix.sync.aligned.m8n8.x2.trans.shared.b16 {%0,%1}, [%2];"
                 : "=r"(r[0]), "=r"(r[1]) : "r"(a));
}
__device__ __forceinline__ void mma16816(float* c, const uint32_t* a, const uint32_t* b) {
    asm volatile(
        "mma.sync.aligned.m16n8k16.row.col.f32.bf16.bf16.f32 "
        "{%0,%1,%2,%3}, {%4,%5,%6,%7}, {%8,%9}, {%0,%1,%2,%3};"
        : "+f"(c[0]), "+f"(c[1]), "+f"(c[2]), "+f"(c[3])
        : "r"(a[0]), "r"(a[1]), "r"(a[2]), "r"(a[3]), "r"(b[0]), "r"(b[1]));
}
__device__ __forceinline__ uint2 cvt_f4_bf16x4(float4 v) {
    __nv_bfloat162 lo = __float22bfloat162_rn(make_float2(v.x, v.y));
    __nv_bfloat162 hi = __float22bfloat162_rn(make_float2(v.z, v.w));
    return make_uint2(*(uint32_t*)&lo, *(uint32_t*)&hi);
}
__device__ __forceinline__ uint32_t cvt2(float2 v) {
    __nv_bfloat162 t = __float22bfloat162_rn(v);
    return *(uint32_t*)&t;
}

#define NCHUNK (NF/64)   // 32
#define SCHUNK 32
#define ONE2 0x3F803F80u
#define BSTAGE 13312                      // 104 rows x 128 B
#define FAT_SMEM (1024 + 3*BSTAGE)        // 40960; sums side uses 37888

// ===== setup (single launch): prep W^T bf16 + zero sums + zero misc ======
// grid = 1089: [0,832) prep_wb (104*2048), [832,1088) zero g_sums, 1088 misc
__global__ void setup_kernel(const float* __restrict__ W) {
    const int bx = blockIdx.x, tid = threadIdx.x;
    if (bx < 832) {
        int i = bx*256 + tid;              // 0..212991
        int n = i >> 11;
        int k = i & (NF-1);
        float v = (n < NL) ? W[(size_t)k*NL + n] : 0.f;
        g_Wb[i] = __float2bfloat16(v);
    } else if (bx < 1088) {
        int base = (bx - 832)*256 + tid;
        for (int i = base; i < NE*NL*NF; i += 256*256)
            g_sums[i] = 0.f;
    } else {
        if (tid < NE*NL) g_counts[tid] = 0.f;
        if (tid == 0) { g_ce = 0.0; g_done = 0u; }
    }
}

// ============ fat kernel: CE GEMM + sums GEMM (counts fused) =============
// grid = 512: even -> CE tile M=128 (bx>>1), odd -> sums tile (bx>>1)
__global__ void __launch_bounds__(256, 2)
fat_kernel(const float* __restrict__ feats,
           const int*   __restrict__ y,
           const float* __restrict__ b) {
    const int bx  = blockIdx.x;
    const int tid = threadIdx.x;

    extern __shared__ char smx[];
    const uint32_t tile0 = (smem_u32(smx) + 1023u) & ~1023u;
    const int wid  = tid >> 5;
    const int lane = tid & 31;
    const int lq   = lane & 3;
    const int lr4  = lane >> 2;
    const float4* fv = (const float4*)feats;

    if ((bx & 1) == 0) {
        // ====== CE GEMM: warp = 16-row band x full 104 cols (13 tiles) ====
        const uint32_t tB[3] = { tile0, tile0 + BSTAGE, tile0 + 2*BSTAGE };
        __shared__ float bias_s[NPAD];
        __shared__ float redw[8];

        const int m0 = (bx >> 1) * 128;
        if (tid < NPAD) bias_s[tid] = (tid < NL) ? b[tid] : 0.f;

        float acc[13][4];
        #pragma unroll
        for (int nt = 0; nt < 13; nt++)
            #pragma unroll
            for (int j = 0; j < 4; j++) acc[nt][j] = 0.f;

        // A: direct-from-global per warp. rows band*16+lr4 (+8)
        const float* aptr0 = feats + (size_t)(m0 + wid*16 + lr4) * NF + 2*lq;
        const float* aptr1 = aptr0 + 8*(size_t)NF;
        float2 sa[16];

        auto loadA = [&](int kt, int jlo, int jhi) {
            #pragma unroll
            for (int j = jlo; j < jhi; j++) {
                sa[2*j]   = *(const float2*)(aptr0 + kt*64 + 8*j);
                sa[2*j+1] = *(const float2*)(aptr1 + kt*64 + 8*j);
            }
        };
        auto issueB = [&](int kt, int stg) {       // 104 n x 64 k = 832 cp16
            #pragma unroll
            for (int i = 0; i < 4; i++) {
                int idx = i*256 + tid;
                if (idx < 832) {
                    int n = idx >> 3, q = idx & 7;
                    cp16(tB[stg] + swz128((uint32_t)(n*128 + q*16)),
                         g_Wb + (size_t)n*NF + kt*64 + q*8);
                }
            }
            cp_commit();
        };

        const int l7    = lane & 7;
        const int khalf = (lane >> 3) & 1;
        const int npair = (lane >> 4) & 1;

        issueB(0, 0);
        issueB(1, 1);
        loadA(0, 0, 8);

        for (int kt = 0; kt < NCHUNK; kt++) {
            const int sb = kt % 3;
            if (kt + 1 < NCHUNK) cp_wait1(); else cp_wait0();
            __syncthreads();
            if (kt + 2 < NCHUNK) issueB(kt + 2, (kt + 2) % 3);
            const bool more = (kt + 1 < NCHUNK);

            #pragma unroll
            for (int s = 0; s < 4; s++) {
                uint32_t af[4];
                af[0] = cvt2(sa[4*s + 0]);
                af[1] = cvt2(sa[4*s + 1]);
                af[2] = cvt2(sa[4*s + 2]);
                af[3] = cvt2(sa[4*s + 3]);
                uint32_t bf[13][2];
                #pragma unroll
                for (int nt = 0; nt < 12; nt += 2) {
                    uint32_t row = (uint32_t)(nt*8 + npair*8 + l7);
                    uint32_t boff = (uint32_t)(s*32 + khalf*16);
                    uint32_t r4[4];
                    ldm_x4(r4, tB[sb] + swz128(row*128 + boff));
                    bf[nt][0] = r4[0];   bf[nt][1] = r4[1];
                    bf[nt+1][0] = r4[2]; bf[nt+1][1] = r4[3];
                }
                {   // 13th tile via x2 (addresses from lanes 0-15)
                    uint32_t row = (uint32_t)(96 + l7);
                    uint32_t boff = (uint32_t)(s*32 + khalf*16);
                    ldm_x2(bf[12], tB[sb] + swz128(row*128 + boff));
                }
                if (s == 1 && more) loadA(kt + 1, 0, 4);
                #pragma unroll
                for (int nt = 0; nt < 13; nt++)
                    mma16816(acc[nt], af, bf[nt]);
                if (s == 3 && more) loadA(kt + 1, 4, 8);
            }
        }

        // -------- warp-local CE epilogue --------
        float ce = 0.f;
        #pragma unroll
        for (int h = 0; h < 2; h++) {
            int row = m0 + wid*16 + h*8 + lr4;
            int yv = y[row];
            float mx = -1e30f, own = 0.f;
            #pragma unroll
            for (int nt = 0; nt < 13; nt++) {
                #pragma unroll
                for (int j = 0; j < 2; j++) {
                    int gc = nt*8 + 2*lq + j;
                    float v = acc[nt][h*2 + j] + bias_s[gc];
                    if (gc >= NL) v = -1e30f;
                    mx = fmaxf(mx, v);
                    if (gc == yv) own = v;
                }
            }
            mx = fmaxf(mx, __shfl_xor_sync(0xffffffffu, mx, 1));
            mx = fmaxf(mx, __shfl_xor_sync(0xffffffffu, mx, 2));
            own += __shfl_xor_sync(0xffffffffu, own, 1);
            own += __shfl_xor_sync(0xffffffffu, own, 2);
            float se = 0.f;
            #pragma unroll
            for (int nt = 0; nt < 13; nt++) {
                #pragma unroll
                for (int j = 0; j < 2; j++) {
                    int gc = nt*8 + 2*lq + j;
                    float v = acc[nt][h*2 + j] + bias_s[gc];
                    if (gc < NL) se += __expf(v - mx);
                }
            }
            se += __shfl_xor_sync(0xffffffffu, se, 1);
            se += __shfl_xor_sync(0xffffffffu, se, 2);
            if (lq == 0) ce += mx + __logf(se) - own;
        }
        #pragma unroll
        for (int o = 16; o > 0; o >>= 1)
            ce += __shfl_xor_sync(0xffffffffu, ce, o);
        if (lane == 0) redw[wid] = ce;
        __syncthreads();
        if (tid == 0) {
            float t = 0.f;
            #pragma unroll
            for (int w = 0; w < 8; w++) t += redw[w];
            atomicAdd(&g_ce, (double)t);
        }
    } else {
        // ====== sums GEMM: sums[e] = onehot(y[e])^T [L,B] @ feats[e] ======
        const uint32_t tF[2] = { tile0, tile0 + 16384 };
        uint32_t* sy16 = (uint32_t*)(smx + (tile0 - smem_u32(smx)) + 32768);

        const int blk = bx >> 1;
        const int n0  = (blk & 15) * 128;
        const int e   = (blk >> 4) & 3;
        const int bz  = (blk >> 6) * 2048;
        const int wm  = wid >> 1;
        const int wn  = wid & 1;
        // warps with wm==3 only need mt=0 (labels 112-127 all >= NL)
        const int mtmax = (wm == 3) ? 1 : 2;

        {
            const int* yp = y + e*NB + bz;
            for (int j = tid; j < 1024; j += 256)
                sy16[j] = (uint32_t)yp[2*j] | ((uint32_t)yp[2*j + 1] << 16);
        }

        float acc[2][8][4];
        #pragma unroll
        for (int mt = 0; mt < 2; mt++)
            #pragma unroll
            for (int nt = 0; nt < 8; nt++)
                #pragma unroll
                for (int j = 0; j < 4; j++) acc[mt][nt][j] = 0.f;

        uint2 st[8];
        auto load_regs = [&](int kt) {
            #pragma unroll
            for (int i = 0; i < 8; i++) {
                int idx = i*256 + tid;
                int row = idx >> 5, q = idx & 31;
                st[i] = cvt_f4_bf16x4(
                    fv[(size_t)(e*NB + bz + kt*64 + row)*(NF/4) + (n0 >> 2) + q]);
            }
        };
        auto sts_regs = [&](int s) {
            #pragma unroll
            for (int i = 0; i < 8; i++) {
                int idx = i*256 + tid;
                int row = idx >> 5, q = idx & 31;
                asm volatile("st.shared.v2.u32 [%0], {%1, %2};"
                             :: "r"(tF[s] + swz256((uint32_t)(row*256 + q*8))),
                                "r"(st[i].x), "r"(st[i].y) : "memory");
            }
        };

        load_regs(0);

        for (int kt = 0; kt < SCHUNK; kt++) {
            const int s = kt & 1;
            sts_regs(s);
            if (kt + 1 < SCHUNK) load_regs(kt + 1);
            __syncthreads();

            #pragma unroll
            for (int k16 = 0; k16 < 4; k16++) {
                uint32_t bfr[8][2];
                {
                    int rr = k16*16 + (lane & 15);
                    #pragma unroll
                    for (int nt = 0; nt < 8; nt++) {
                        uint32_t cn = (uint32_t)(wn*8 + nt);
                        ldm_x2t(bfr[nt], tF[s] + swz256((uint32_t)(rr*256) + cn*16));
                    }
                }
                uint32_t yp0 = sy16[kt*32 + k16*8 + lq];
                uint32_t yp1 = sy16[kt*32 + k16*8 + 4 + lq];
                for (int mt = 0; mt < mtmax; mt++) {
                    int lm = wm*32 + mt*16 + lr4;
                    uint32_t ll  = (uint32_t)lm | ((uint32_t)lm << 16);
                    uint32_t ll8 = ll + 0x00080008u;
                    uint32_t af[4];
                    af[0] = __vcmpeq2(yp0, ll)  & ONE2;
                    af[1] = __vcmpeq2(yp0, ll8) & ONE2;
                    af[2] = __vcmpeq2(yp1, ll)  & ONE2;
                    af[3] = __vcmpeq2(yp1, ll8) & ONE2;
                    #pragma unroll
                    for (int nt = 0; nt < 8; nt++)
                        mma16816(acc[mt][nt], af, bfr[nt]);
                }
            }
        }

        #pragma unroll
        for (int mt = 0; mt < 2; mt++) {
            #pragma unroll
            for (int h = 0; h < 2; h++) {
                int l = wm*32 + mt*16 + h*8 + lr4;
                if (l < NL) {
                    #pragma unroll
                    for (int nt = 0; nt < 8; nt++) {
                        int f = n0 + wn*64 + nt*8 + 2*lq;
                        float* dst = &g_sums[((size_t)e*NL + l)*NF + f];
                        atomicAdd(dst,     acc[mt][nt][h*2 + 0]);
                        atomicAdd(dst + 1, acc[mt][nt][h*2 + 1]);
                    }
                }
            }
        }

        // ---- fused label counts (one F-chunk CTA per (e, bz)) ----
        if ((blk & 15) == 0) {
            for (int j = tid; j < 1024; j += 256) {
                uint32_t u = sy16[j];
                atomicAdd(&g_counts[e*NL + (int)(u & 0xFFFFu)], 1.0f);
                atomicAdd(&g_counts[e*NL + (int)(u >> 16)],     1.0f);
            }
        }
    }
}

// ======== variance per (env,label) + fused final combine ================
__global__ void var_combine_kernel(float* __restrict__ out) {
    const int el = blockIdx.x;
    const int tid = threadIdx.x;
    float cnt = g_counts[el];
    float inv = 1.0f / fmaxf(cnt, 1.0f);
    const float* s = g_sums + (size_t)el * NF;

    float sum = 0.f, sq = 0.f;
    for (int f = tid; f < NF; f += 256) {
        float m = s[f] * inv;
        sum += m;
        sq  = fmaf(m, m, sq);
    }
    __shared__ float s1[256], s2[256];
    s1[tid] = sum; s2[tid] = sq;
    __syncthreads();
    for (int o = 128; o > 0; o >>= 1) {
        if (tid < o) { s1[tid] += s1[tid+o]; s2[tid] += s2[tid+o]; }
        __syncthreads();
    }
    __shared__ bool last;
    if (tid == 0) {
        float S = s1[0], Q = s2[0];
        float mu = S / (float)NF;
        g_var[el]   = (Q - S*mu) / (float)(NF - 1);
        g_visit[el] = (cnt > 0.f) ? 1.f : 0.f;
        __threadfence();
        unsigned v = atomicAdd(&g_done, 1u);
        last = (v == (unsigned)(NE*NL - 1));
    }
    __syncthreads();
    if (!last) return;
    __threadfence();

    float pl_sel = 0.f, sel = 0.f;
    if (tid < NL) {
        float nvis = 0.f, vv = 0.f;
        #pragma unroll
        for (int e = 0; e < NE; e++) {
            float vis = g_visit[e*NL + tid];
            nvis += vis;
            vv   += g_var[e*NL + tid] * vis;
        }
        float per = vv / fmaxf(nvis, 1.0f);
        sel    = (nvis > 1.5f) ? 1.f : 0.f;
        pl_sel = per * sel;
    }
    __syncthreads();
    s1[tid] = pl_sel; s2[tid] = sel;
    __syncthreads();
    for (int o = 128; o > 0; o >>= 1) {
        if (tid < o) { s1[tid] += s1[tid+o]; s2[tid] += s2[tid+o]; }
        __syncthreads();
    }
    if (tid == 0) {
        float mean_loss = LAM * s1[0] / fmaxf(s2[0], 1.0f);
        out[0] = mean_loss + (float)(g_ce / (double)NEB);
    }
}

// ---------------- launch ----------------
extern "C" void kernel_launch(void* const* d_in, const int* in_sizes, int n_in,
                              void* d_out, int out_size) {
    const float* feats = (const float*)d_in[0];
    const int*   y     = (const int*)  d_in[1];
    const float* W     = (const float*)d_in[2];
    const float* b     = (const float*)d_in[3];
    float* out = (float*)d_out;

    cudaFuncSetAttribute(fat_kernel, cudaFuncAttributeMaxDynamicSharedMemorySize, FAT_SMEM);

    setup_kernel      <<<1089, 256>>>(W);
    fat_kernel        <<<512, 256, FAT_SMEM>>>(feats, y, b);
    var_combine_kernel<<<NE*NL, 256>>>(out);
}